// round 5
// baseline (speedup 1.0000x reference)
#include <cuda_runtime.h>

#define NB 64
#define NE 64
#define NC 64
#define NO 20

// packed f32x2 FMA: acc = a*b + acc (two independent fp32 lanes in one b64 reg)
#define FMA2(acc, a, b) asm("fma.rn.f32x2 %0, %1, %2, %0;" : "+l"(acc) : "l"(a), "l"(b))

// ---------------- device scratch (no allocs allowed) ----------------
__device__ float g_h1[(size_t)NB*NE*14*14*NC];   // conv1 raw relu out (205 MB)
__device__ float g_h2[(size_t)NB*NE*7*7*NC];     // conv2 raw relu out
__device__ float g_h3[(size_t)NB*NE*4*4*NC];     // conv3 raw relu out
__device__ float g_feat[NB*NE*NC];               // max-pooled raw conv4 relu
__device__ float g_sum[4*NC];
__device__ float g_sumsq[4*NC];
__device__ float g_scale[4*NC];                  // rsqrt(var+eps)
__device__ float g_bias[4*NC];                   // -mean*scale

// ---------------- zero stats + feat ----------------
__global__ void zero_kernel() {
    int i = blockIdx.x * 256 + threadIdx.x;
    if (i < 4*NC) { g_sum[i] = 0.f; g_sumsq[i] = 0.f; }
    if (i < NB*NE*NC) g_feat[i] = 0.f;
}

// ---------------- conv1: Cin=1, 28x28 -> 14x14x64 ----------------
__global__ __launch_bounds__(256) void conv1_kernel(const float* __restrict__ x,
                                                    const float* __restrict__ k1) {
    __shared__ float s_in[30*30];
    __shared__ float s_sum[NC];
    __shared__ float s_sq[NC];
    int be = blockIdx.x;
    int t = threadIdx.x;
    for (int i = t; i < 900; i += 256) s_in[i] = 0.f;
    if (t < NC) { s_sum[t] = 0.f; s_sq[t] = 0.f; }
    __syncthreads();
    const float* xp = x + (size_t)be * 784;
    for (int i = t; i < 784; i += 256) {
        int r = i / 28, c = i - r*28;
        s_in[(r+1)*30 + c + 1] = xp[i];
    }
    int cg = t & 15, ig = t >> 4;
    int b = be >> 6;
    float4 w[9];
    const float4* kp = (const float4*)(k1 + (size_t)b * 576);
    #pragma unroll
    for (int j = 0; j < 9; j++) w[j] = kp[j*16 + cg];
    __syncthreads();
    float ls0=0,ls1=0,ls2=0,ls3=0, lq0=0,lq1=0,lq2=0,lq3=0;
    float* outp = g_h1 + (size_t)be * 196 * 64;
    for (int p = ig; p < 196; p += 16) {
        int oy = p / 14, ox = p - oy*14;
        float a0=0,a1=0,a2=0,a3=0;
        #pragma unroll
        for (int ky = 0; ky < 3; ky++)
        #pragma unroll
        for (int kx = 0; kx < 3; kx++) {
            float v = s_in[(2*oy+ky)*30 + 2*ox + kx];
            float4 ww = w[ky*3+kx];
            a0 = fmaf(v, ww.x, a0); a1 = fmaf(v, ww.y, a1);
            a2 = fmaf(v, ww.z, a2); a3 = fmaf(v, ww.w, a3);
        }
        a0 = fmaxf(a0, 0.f); a1 = fmaxf(a1, 0.f);
        a2 = fmaxf(a2, 0.f); a3 = fmaxf(a3, 0.f);
        ls0+=a0; ls1+=a1; ls2+=a2; ls3+=a3;
        lq0+=a0*a0; lq1+=a1*a1; lq2+=a2*a2; lq3+=a3*a3;
        ((float4*)(outp + p*64))[cg] = make_float4(a0,a1,a2,a3);
    }
    int co4 = cg*4;
    atomicAdd(&s_sum[co4+0], ls0); atomicAdd(&s_sum[co4+1], ls1);
    atomicAdd(&s_sum[co4+2], ls2); atomicAdd(&s_sum[co4+3], ls3);
    atomicAdd(&s_sq[co4+0], lq0); atomicAdd(&s_sq[co4+1], lq1);
    atomicAdd(&s_sq[co4+2], lq2); atomicAdd(&s_sq[co4+3], lq3);
    __syncthreads();
    if (t < NC) {
        atomicAdd(&g_sum[t], s_sum[t]);
        atomicAdd(&g_sumsq[t], s_sq[t]);
    }
}

// ---------------- per-layer BN stats finalize ----------------
__global__ void finalize_kernel(int layer, float invN) {
    int c = threadIdx.x;
    float s = g_sum[layer*NC + c];
    float q = g_sumsq[layer*NC + c];
    float m = s * invN;
    float v = q * invN - m*m;
    float sc = rsqrtf(v + 1e-3f);
    g_scale[layer*NC + c] = sc;
    g_bias[layer*NC + c] = -m * sc;
}

// ---------------- generic conv layers 2-4 (implicit GEMM per task) ----------------
// LNUM=1: h1(14x14) -> h2(7x7); LNUM=2: h2 -> h3(4x4); LNUM=3: h3 -> g_feat (max), LAST
template<int LNUM>
__global__ __launch_bounds__(256, 2) void conv_kernel(const float* __restrict__ kw) {
    constexpr int HIN    = (LNUM==1) ? 14 : (LNUM==2) ? 7 : 4;
    constexpr int HOUT   = (LNUM==1) ? 7  : (LNUM==2) ? 4 : 2;
    constexpr int SPREV  = LNUM - 1;
    constexpr int TILE_M = (LNUM==3) ? 64 : 256;
    constexpr int IT     = (LNUM==3) ? 2  : 8;
    constexpr bool LAST  = (LNUM==3);
    constexpr int POS    = HOUT*HOUT;
    constexpr int MTASK  = NE*POS;

    extern __shared__ float sm[];
    float* sA   = sm;                    // TILE_M rows x 68 floats (k-contiguous)
    float* sBt  = sm + TILE_M*68;        // 64 co rows x 68 floats (k-contiguous, transposed)
    float* s_sc = sBt + 64*68;
    float* s_bi = s_sc + 64;
    float* s_sum= s_bi + 64;
    float* s_sq = s_sum + 64;
    int*   s_ri = (int*)(s_sq + 64);     // TILE_M row-info entries

    const float* h_prev = (LNUM==1) ? g_h1 : (LNUM==2) ? g_h2 : g_h3;
    float* h_out        = (LNUM==1) ? g_h2 : g_h3;

    int b  = blockIdx.y;
    int m0 = blockIdx.x * TILE_M;
    int t  = threadIdx.x;
    if (t < 64) {
        s_sc[t] = g_scale[SPREV*NC + t];
        s_bi[t] = g_bias[SPREV*NC + t];
        s_sum[t] = 0.f; s_sq[t] = 0.f;
    }
    if (t < TILE_M) {
        int gi  = m0 + t;
        int gic = min(gi, MTASK-1);
        int e  = gic / POS;
        int p  = gic - e*POS;
        s_ri[t] = (e << 16) | ((p / HOUT) << 8) | (p % HOUT);
    }

    // loader: 16 threads per item row (coalesced 256B per row)
    int lr = t >> 4;     // row-within-pass (0..15)
    int lj = t & 15;     // float4 (channel group) within row

    // compute: thread owns couts {cg + jj*8 : jj=0..7}, items ig + i*32
    int cg = t & 7, ig = t >> 3;
    unsigned long long acc2[IT][8];   // packed (even-k partial, odd-k partial)
    #pragma unroll
    for (int i = 0; i < IT; i++)
        #pragma unroll
        for (int j = 0; j < 8; j++) acc2[i][j] = 0ull;

    __syncthreads();

    // BN fold coefficients for this loader's channel group (invariant over kk)
    float4 f_s = ((const float4*)s_sc)[lj];
    float4 f_b = ((const float4*)s_bi)[lj];

    const float4* wtask = (const float4*)(kw + (size_t)b*9*64*64);
    const float* taskin = h_prev + (size_t)b*NE*HIN*HIN*64;

    for (int kk = 0; kk < 9; kk++) {
        int ky = kk/3, kx = kk - ky*3;
        // ---- B tile: read [k][co] from gmem, store transposed [co][k] ----
        #pragma unroll
        for (int j = 0; j < 4; j++) {
            int idx = j*256 + t;
            float4 v = wtask[kk*1024 + idx];
            int k   = idx >> 4;          // 0..63
            int co0 = (idx & 15) * 4;    // 0,4,..,60
            sBt[(co0+0)*68 + k] = v.x;
            sBt[(co0+1)*68 + k] = v.y;
            sBt[(co0+2)*68 + k] = v.z;
            sBt[(co0+3)*68 + k] = v.w;
        }
        // ---- A tile: coalesced im2col gather + BN-fold ----
        #pragma unroll
        for (int rr = 0; rr < TILE_M/16; rr++) {
            int row  = rr*16 + lr;
            int info = s_ri[row];
            int e  = info >> 16;
            int oy = (info >> 8) & 255;
            int ox = info & 255;
            int iy = 2*oy - 1 + ky;
            int ix = 2*ox - 1 + kx;
            float4 v;
            if ((unsigned)iy < (unsigned)HIN && (unsigned)ix < (unsigned)HIN) {
                v = ((const float4*)(taskin + ((size_t)e*HIN*HIN + iy*HIN + ix)*64))[lj];
                v.x = fmaf(v.x, f_s.x, f_b.x);
                v.y = fmaf(v.y, f_s.y, f_b.y);
                v.z = fmaf(v.z, f_s.z, f_b.z);
                v.w = fmaf(v.w, f_s.w, f_b.w);
            } else {
                v = make_float4(0.f,0.f,0.f,0.f);
            }
            ((float4*)(sA + row*68))[lj] = v;
        }
        __syncthreads();
        // ---- GEMM: 64-deep k via packed-pair FFMA2 ----
        const float* ap = sA  + ig*68;
        const float* bp = sBt + cg*68;
        #pragma unroll 4
        for (int k4 = 0; k4 < 64; k4 += 4) {
            ulonglong2 av[IT];   // .x = pack(k4,k4+1), .y = pack(k4+2,k4+3)
            #pragma unroll
            for (int i = 0; i < IT; i++)
                av[i] = *(const ulonglong2*)(ap + i*32*68 + k4);
            #pragma unroll
            for (int jj = 0; jj < 8; jj++) {
                unsigned long long b0 = *(const unsigned long long*)(bp + jj*544 + k4);
                unsigned long long b1 = *(const unsigned long long*)(bp + jj*544 + k4 + 2);
                #pragma unroll
                for (int i = 0; i < IT; i++) {
                    FMA2(acc2[i][jj], av[i].x, b0);
                    FMA2(acc2[i][jj], av[i].y, b1);
                }
            }
        }
        __syncthreads();
    }

    // ---- epilogue: combine halves, relu, stats, store / max-pool ----
    float lsum[8], lsq[8];
    #pragma unroll
    for (int j = 0; j < 8; j++) { lsum[j] = 0.f; lsq[j] = 0.f; }
    #pragma unroll
    for (int i = 0; i < IT; i++) {
        int g = m0 + ig + i*32;
        if (g < MTASK) {
            float vv[8];
            #pragma unroll
            for (int jj = 0; jj < 8; jj++) {
                float lo, hi;
                asm("mov.b64 {%0,%1}, %2;" : "=f"(lo), "=f"(hi) : "l"(acc2[i][jj]));
                float v = fmaxf(lo + hi, 0.f);
                vv[jj] = v;
                lsum[jj] += v;
                lsq[jj]  += v*v;
            }
            if (!LAST) {
                float* dst = h_out + ((size_t)b*MTASK + g)*64 + cg;
                #pragma unroll
                for (int jj = 0; jj < 8; jj++) dst[jj*8] = vv[jj];
            } else {
                int ee = g / POS;
                int* fp = (int*)(g_feat + ((size_t)(b*NE + ee))*64 + cg);
                #pragma unroll
                for (int jj = 0; jj < 8; jj++)
                    atomicMax(&fp[jj*8], __float_as_int(vv[jj]));  // relu>=0: int order == float order
            }
        }
    }
    #pragma unroll
    for (int jj = 0; jj < 8; jj++) {
        atomicAdd(&s_sum[cg + jj*8], lsum[jj]);
        atomicAdd(&s_sq[cg + jj*8],  lsq[jj]);
    }
    __syncthreads();
    if (t < 64) {
        atomicAdd(&g_sum[LNUM*NC + t],   s_sum[t]);
        atomicAdd(&g_sumsq[LNUM*NC + t], s_sq[t]);
    }
}

// ---------------- readout: normalize pooled feats, per-task matmul ----------------
__global__ __launch_bounds__(256) void readout_kernel(const float* __restrict__ w_ro,
                                                      float* __restrict__ out) {
    __shared__ float s_w[64*20];
    __shared__ float s_f[64*64];
    int b = blockIdx.x, t = threadIdx.x;
    for (int i = t; i < 1280; i += 256) s_w[i] = w_ro[(size_t)b*1280 + i];
    const float* fp = g_feat + (size_t)b*4096;
    for (int i = t; i < 4096; i += 256) {
        int c = i & 63;
        s_f[i] = fmaf(fp[i], g_scale[3*64+c], g_bias[3*64+c]);
    }
    __syncthreads();
    for (int idx = t; idx < 1280; idx += 256) {
        int e = idx/20, o = idx - e*20;
        float s = 0.f;
        const float* fe = s_f + e*64;
        #pragma unroll 16
        for (int c = 0; c < 64; c++) s = fmaf(fe[c], s_w[c*20+o], s);
        out[(size_t)b*1280 + idx] = s;
    }
}

// ---------------- launch ----------------
extern "C" void kernel_launch(void* const* d_in, const int* in_sizes, int n_in,
                              void* d_out, int out_size) {
    const float* x  = (const float*)d_in[0];
    const float* k1 = (const float*)d_in[1];
    const float* k2 = (const float*)d_in[2];
    const float* k3 = (const float*)d_in[3];
    const float* k4 = (const float*)d_in[4];
    const float* w  = (const float*)d_in[5];
    float* out = (float*)d_out;
    (void)in_sizes; (void)n_in; (void)out_size;

    const int smem12 = 256*68*4 + 64*68*4 + 4*64*4 + 256*4;   // A + Bt + stats + rowinfo
    const int smem3  = 64*68*4  + 64*68*4 + 4*64*4 + 64*4;
    cudaFuncSetAttribute(conv_kernel<1>, cudaFuncAttributeMaxDynamicSharedMemorySize, smem12);
    cudaFuncSetAttribute(conv_kernel<2>, cudaFuncAttributeMaxDynamicSharedMemorySize, smem12);
    cudaFuncSetAttribute(conv_kernel<3>, cudaFuncAttributeMaxDynamicSharedMemorySize, smem3);

    zero_kernel<<<1024, 256>>>();
    conv1_kernel<<<NB*NE, 256>>>(x, k1);
    finalize_kernel<<<1, 64>>>(0, 1.f/(NB*NE*196.f));
    conv_kernel<1><<<dim3(13, NB), 256, smem12>>>(k2);
    finalize_kernel<<<1, 64>>>(1, 1.f/(NB*NE*49.f));
    conv_kernel<2><<<dim3(4, NB), 256, smem12>>>(k3);
    finalize_kernel<<<1, 64>>>(2, 1.f/(NB*NE*16.f));
    conv_kernel<3><<<dim3(4, NB), 256, smem3>>>(k4);
    finalize_kernel<<<1, 64>>>(3, 1.f/(NB*NE*4.f));
    readout_kernel<<<NB, 256>>>(w, out);
}

// round 6
// speedup vs baseline: 2.5381x; 2.5381x over previous
#include <cuda_runtime.h>

#define NB 64
#define NE 64
#define NC 64
#define NO 20

// packed f32x2 FMA: acc = a*b + acc (two independent fp32 lanes in one b64 reg)
#define FMA2(acc, a, b) asm("fma.rn.f32x2 %0, %1, %2, %0;" : "+l"(acc) : "l"(a), "l"(b))

// ---------------- device scratch (no allocs allowed) ----------------
__device__ float g_h1[(size_t)NB*NE*14*14*NC];   // conv1 raw relu out (205 MB)
__device__ float g_h2[(size_t)NB*NE*7*7*NC];     // conv2 raw relu out
__device__ float g_h3[(size_t)NB*NE*4*4*NC];     // conv3 raw relu out
__device__ float g_feat[NB*NE*NC];               // max-pooled raw conv4 relu
__device__ float g_kT[3][NB][9][64][64];         // weights transposed to [co][ci] (28 MB)
__device__ float g_sum[4*NC];
__device__ float g_sumsq[4*NC];
__device__ float g_scale[4*NC];                  // rsqrt(var+eps)
__device__ float g_bias[4*NC];                   // -mean*scale

// ---------------- zero stats + feat ----------------
__global__ void zero_kernel() {
    int i = blockIdx.x * 256 + threadIdx.x;
    if (i < 4*NC) { g_sum[i] = 0.f; g_sumsq[i] = 0.f; }
    if (i < NB*NE*NC) g_feat[i] = 0.f;
}

// ---------------- weight transpose: kw[b][kk][ci][co] -> g_kT[layer][b][kk][co][ci] ----------------
__global__ __launch_bounds__(256) void wtrans_kernel(const float* __restrict__ kw, int layer) {
    __shared__ float s[64*65];
    int b  = blockIdx.x >> 4;          // grid = 64*9 packed as (b*16 + kk) with kk<9 guard
    int kk = blockIdx.x & 15;
    if (kk >= 9) return;
    int t = threadIdx.x;
    const float* src = kw + ((size_t)b*9 + kk)*4096;
    #pragma unroll
    for (int p = 0; p < 16; p++) {
        int idx = p*256 + t;           // idx = ci*64 + co
        int ci = idx >> 6, co = idx & 63;
        s[co*65 + ci] = src[idx];      // coalesced read, conflict-free scatter
    }
    __syncthreads();
    float* dst = &g_kT[layer][b][kk][0][0];
    #pragma unroll
    for (int p = 0; p < 16; p++) {
        int idx = p*256 + t;           // idx = co*64 + ci
        int co = idx >> 6, ci = idx & 63;
        dst[idx] = s[co*65 + ci];      // coalesced write
    }
}

// ---------------- conv1: Cin=1, 28x28 -> 14x14x64 ----------------
__global__ __launch_bounds__(256) void conv1_kernel(const float* __restrict__ x,
                                                    const float* __restrict__ k1) {
    __shared__ float s_in[30*30];
    __shared__ float s_sum[NC];
    __shared__ float s_sq[NC];
    int be = blockIdx.x;
    int t = threadIdx.x;
    for (int i = t; i < 900; i += 256) s_in[i] = 0.f;
    if (t < NC) { s_sum[t] = 0.f; s_sq[t] = 0.f; }
    __syncthreads();
    const float* xp = x + (size_t)be * 784;
    for (int i = t; i < 784; i += 256) {
        int r = i / 28, c = i - r*28;
        s_in[(r+1)*30 + c + 1] = xp[i];
    }
    int cg = t & 15, ig = t >> 4;
    int b = be >> 6;
    float4 w[9];
    const float4* kp = (const float4*)(k1 + (size_t)b * 576);
    #pragma unroll
    for (int j = 0; j < 9; j++) w[j] = kp[j*16 + cg];
    __syncthreads();
    float ls0=0,ls1=0,ls2=0,ls3=0, lq0=0,lq1=0,lq2=0,lq3=0;
    float* outp = g_h1 + (size_t)be * 196 * 64;
    for (int p = ig; p < 196; p += 16) {
        int oy = p / 14, ox = p - oy*14;
        float a0=0,a1=0,a2=0,a3=0;
        #pragma unroll
        for (int ky = 0; ky < 3; ky++)
        #pragma unroll
        for (int kx = 0; kx < 3; kx++) {
            float v = s_in[(2*oy+ky)*30 + 2*ox + kx];
            float4 ww = w[ky*3+kx];
            a0 = fmaf(v, ww.x, a0); a1 = fmaf(v, ww.y, a1);
            a2 = fmaf(v, ww.z, a2); a3 = fmaf(v, ww.w, a3);
        }
        a0 = fmaxf(a0, 0.f); a1 = fmaxf(a1, 0.f);
        a2 = fmaxf(a2, 0.f); a3 = fmaxf(a3, 0.f);
        ls0+=a0; ls1+=a1; ls2+=a2; ls3+=a3;
        lq0+=a0*a0; lq1+=a1*a1; lq2+=a2*a2; lq3+=a3*a3;
        ((float4*)(outp + p*64))[cg] = make_float4(a0,a1,a2,a3);
    }
    int co4 = cg*4;
    atomicAdd(&s_sum[co4+0], ls0); atomicAdd(&s_sum[co4+1], ls1);
    atomicAdd(&s_sum[co4+2], ls2); atomicAdd(&s_sum[co4+3], ls3);
    atomicAdd(&s_sq[co4+0], lq0); atomicAdd(&s_sq[co4+1], lq1);
    atomicAdd(&s_sq[co4+2], lq2); atomicAdd(&s_sq[co4+3], lq3);
    __syncthreads();
    if (t < NC) {
        atomicAdd(&g_sum[t], s_sum[t]);
        atomicAdd(&g_sumsq[t], s_sq[t]);
    }
}

// ---------------- per-layer BN stats finalize ----------------
__global__ void finalize_kernel(int layer, float invN) {
    int c = threadIdx.x;
    float s = g_sum[layer*NC + c];
    float q = g_sumsq[layer*NC + c];
    float m = s * invN;
    float v = q * invN - m*m;
    float sc = rsqrtf(v + 1e-3f);
    g_scale[layer*NC + c] = sc;
    g_bias[layer*NC + c] = -m * sc;
}

// ---------------- generic conv layers 2-4 (implicit GEMM per task, FFMA2) ----------------
// LNUM=1: h1(14x14) -> h2(7x7); LNUM=2: h2 -> h3(4x4); LNUM=3: h3 -> g_feat (max), LAST
template<int LNUM>
__global__ __launch_bounds__(256, 2) void conv_kernel() {
    constexpr int HIN    = (LNUM==1) ? 14 : (LNUM==2) ? 7 : 4;
    constexpr int HOUT   = (LNUM==1) ? 7  : (LNUM==2) ? 4 : 2;
    constexpr int SPREV  = LNUM - 1;
    constexpr int TILE_M = (LNUM==3) ? 64 : 128;
    constexpr int IT     = (LNUM==3) ? 2  : 4;
    constexpr bool LAST  = (LNUM==3);
    constexpr int POS    = HOUT*HOUT;
    constexpr int MTASK  = NE*POS;

    extern __shared__ float sm[];
    float* sA   = sm;                    // TILE_M rows x 68 floats (k-contiguous)
    float* sBt  = sm + TILE_M*68;        // 64 co rows x 68 floats (k-contiguous)
    float* s_sc = sBt + 64*68;
    float* s_bi = s_sc + 64;
    float* s_sum= s_bi + 64;
    float* s_sq = s_sum + 64;
    int*   s_ri = (int*)(s_sq + 64);     // TILE_M row-info entries

    const float* h_prev = (LNUM==1) ? g_h1 : (LNUM==2) ? g_h2 : g_h3;
    float* h_out        = (LNUM==1) ? g_h2 : g_h3;

    int b  = blockIdx.y;
    int m0 = blockIdx.x * TILE_M;
    int t  = threadIdx.x;
    if (t < 64) {
        s_sc[t] = g_scale[SPREV*NC + t];
        s_bi[t] = g_bias[SPREV*NC + t];
        s_sum[t] = 0.f; s_sq[t] = 0.f;
    }
    if (t < TILE_M) {
        int gi  = m0 + t;
        int gic = min(gi, MTASK-1);
        int e  = gic / POS;
        int p  = gic - e*POS;
        s_ri[t] = (e << 16) | ((p / HOUT) << 8) | (p % HOUT);
    }

    // loader: 16 threads per item row (coalesced 256B per row)
    int lr = t >> 4;     // row-within-pass (0..15)
    int lj = t & 15;     // float4 (channel group) within row

    // compute: thread owns couts {cg + 8*jj : jj=0..7}, items ig + i*32
    int cg = t & 7, ig = t >> 3;
    unsigned long long acc2[IT][8];   // packed (even-k partial, odd-k partial)
    #pragma unroll
    for (int i = 0; i < IT; i++)
        #pragma unroll
        for (int j = 0; j < 8; j++) acc2[i][j] = 0ull;

    __syncthreads();

    // BN fold coefficients for this loader's channel group (invariant over kk)
    float4 f_s = ((const float4*)s_sc)[lj];
    float4 f_b = ((const float4*)s_bi)[lj];

    const float* wT = &g_kT[LNUM-1][b][0][0][0];
    const float* taskin = h_prev + (size_t)b*NE*HIN*HIN*64;

    for (int kk = 0; kk < 9; kk++) {
        int ky = kk/3, kx = kk - ky*3;
        // ---- B tile: pre-transposed [co][k] rows, plain copy into 68-stride rows ----
        #pragma unroll
        for (int j = 0; j < 4; j++) {
            int idx = j*256 + t;           // idx = co*16 + seg
            int co = idx >> 4, seg = idx & 15;
            *(float4*)(sBt + co*68 + seg*4) =
                *(const float4*)(wT + kk*4096 + co*64 + seg*4);
        }
        // ---- A tile: coalesced im2col gather + BN-fold ----
        #pragma unroll
        for (int rr = 0; rr < TILE_M/16; rr++) {
            int row  = rr*16 + lr;
            int info = s_ri[row];
            int e  = info >> 16;
            int oy = (info >> 8) & 255;
            int ox = info & 255;
            int iy = 2*oy - 1 + ky;
            int ix = 2*ox - 1 + kx;
            float4 v;
            if ((unsigned)iy < (unsigned)HIN && (unsigned)ix < (unsigned)HIN) {
                v = ((const float4*)(taskin + ((size_t)e*HIN*HIN + iy*HIN + ix)*64))[lj];
                v.x = fmaf(v.x, f_s.x, f_b.x);
                v.y = fmaf(v.y, f_s.y, f_b.y);
                v.z = fmaf(v.z, f_s.z, f_b.z);
                v.w = fmaf(v.w, f_s.w, f_b.w);
            } else {
                v = make_float4(0.f,0.f,0.f,0.f);
            }
            ((float4*)(sA + row*68))[lj] = v;
        }
        __syncthreads();
        // ---- GEMM: 64-deep k in packed pairs (a_k,a_k+1)x(b_k,b_k+1) via FFMA2 ----
        const float* ap = sA  + ig*68;
        const float* bp = sBt + cg*68;
        #pragma unroll 2
        for (int k2 = 0; k2 < 64; k2 += 2) {
            unsigned long long av[IT];
            #pragma unroll
            for (int i = 0; i < IT; i++)
                av[i] = *(const unsigned long long*)(ap + i*32*68 + k2);
            #pragma unroll
            for (int jj = 0; jj < 8; jj++) {
                unsigned long long bv = *(const unsigned long long*)(bp + jj*544 + k2);
                #pragma unroll
                for (int i = 0; i < IT; i++)
                    FMA2(acc2[i][jj], av[i], bv);
            }
        }
        __syncthreads();
    }

    // ---- epilogue: combine halves, relu, stats, store / max-pool ----
    float lsum[8], lsq[8];
    #pragma unroll
    for (int j = 0; j < 8; j++) { lsum[j] = 0.f; lsq[j] = 0.f; }
    #pragma unroll
    for (int i = 0; i < IT; i++) {
        int g = m0 + ig + i*32;
        if (g < MTASK) {
            float vv[8];
            #pragma unroll
            for (int jj = 0; jj < 8; jj++) {
                float lo, hi;
                asm("mov.b64 {%0,%1}, %2;" : "=f"(lo), "=f"(hi) : "l"(acc2[i][jj]));
                float v = fmaxf(lo + hi, 0.f);
                vv[jj] = v;
                lsum[jj] += v;
                lsq[jj]  += v*v;
            }
            if (!LAST) {
                float* dst = h_out + ((size_t)b*MTASK + g)*64 + cg;
                #pragma unroll
                for (int jj = 0; jj < 8; jj++) dst[jj*8] = vv[jj];
            } else {
                int ee = g / POS;
                int* fp = (int*)(g_feat + ((size_t)(b*NE + ee))*64 + cg);
                #pragma unroll
                for (int jj = 0; jj < 8; jj++)
                    atomicMax(&fp[jj*8], __float_as_int(vv[jj]));  // relu>=0: int order == float order
            }
        }
    }
    #pragma unroll
    for (int jj = 0; jj < 8; jj++) {
        atomicAdd(&s_sum[cg + jj*8], lsum[jj]);
        atomicAdd(&s_sq[cg + jj*8],  lsq[jj]);
    }
    __syncthreads();
    if (t < 64) {
        atomicAdd(&g_sum[LNUM*NC + t],   s_sum[t]);
        atomicAdd(&g_sumsq[LNUM*NC + t], s_sq[t]);
    }
}

// ---------------- readout: normalize pooled feats, per-task matmul ----------------
__global__ __launch_bounds__(256) void readout_kernel(const float* __restrict__ w_ro,
                                                      float* __restrict__ out) {
    __shared__ float s_w[64*20];
    __shared__ float s_f[64*64];
    int b = blockIdx.x, t = threadIdx.x;
    for (int i = t; i < 1280; i += 256) s_w[i] = w_ro[(size_t)b*1280 + i];
    const float* fp = g_feat + (size_t)b*4096;
    for (int i = t; i < 4096; i += 256) {
        int c = i & 63;
        s_f[i] = fmaf(fp[i], g_scale[3*64+c], g_bias[3*64+c]);
    }
    __syncthreads();
    for (int idx = t; idx < 1280; idx += 256) {
        int e = idx/20, o = idx - e*20;
        float s = 0.f;
        const float* fe = s_f + e*64;
        #pragma unroll 16
        for (int c = 0; c < 64; c++) s = fmaf(fe[c], s_w[c*20+o], s);
        out[(size_t)b*1280 + idx] = s;
    }
}

// ---------------- launch ----------------
extern "C" void kernel_launch(void* const* d_in, const int* in_sizes, int n_in,
                              void* d_out, int out_size) {
    const float* x  = (const float*)d_in[0];
    const float* k1 = (const float*)d_in[1];
    const float* k2 = (const float*)d_in[2];
    const float* k3 = (const float*)d_in[3];
    const float* k4 = (const float*)d_in[4];
    const float* w  = (const float*)d_in[5];
    float* out = (float*)d_out;
    (void)in_sizes; (void)n_in; (void)out_size;

    const int smem12 = 128*68*4 + 64*68*4 + 4*64*4 + 128*4;   // 53,760 B
    const int smem3  = 64*68*4  + 64*68*4 + 4*64*4 + 64*4;    // 36,096 B
    cudaFuncSetAttribute(conv_kernel<1>, cudaFuncAttributeMaxDynamicSharedMemorySize, smem12);
    cudaFuncSetAttribute(conv_kernel<2>, cudaFuncAttributeMaxDynamicSharedMemorySize, smem12);
    cudaFuncSetAttribute(conv_kernel<3>, cudaFuncAttributeMaxDynamicSharedMemorySize, smem3);

    zero_kernel<<<1024, 256>>>();
    wtrans_kernel<<<64*16, 256>>>(k2, 0);
    wtrans_kernel<<<64*16, 256>>>(k3, 1);
    wtrans_kernel<<<64*16, 256>>>(k4, 2);
    conv1_kernel<<<NB*NE, 256>>>(x, k1);
    finalize_kernel<<<1, 64>>>(0, 1.f/(NB*NE*196.f));
    conv_kernel<1><<<dim3(25, NB), 256, smem12>>>();
    finalize_kernel<<<1, 64>>>(1, 1.f/(NB*NE*49.f));
    conv_kernel<2><<<dim3(8, NB), 256, smem12>>>();
    finalize_kernel<<<1, 64>>>(2, 1.f/(NB*NE*16.f));
    conv_kernel<3><<<dim3(4, NB), 256, smem3>>>();
    finalize_kernel<<<1, 64>>>(3, 1.f/(NB*NE*4.f));
    readout_kernel<<<NB, 256>>>(w, out);
}

// round 10
// speedup vs baseline: 3.6597x; 1.4419x over previous
#include <cuda_runtime.h>
#include <cuda_bf16.h>
#include <cstdint>

#define NB 64
#define NE 64
#define NC 64
#define NO 20

// ---------------- device scratch (no allocs allowed) ----------------
__device__ float g_h1[(size_t)NB*NE*14*14*NC];   // conv1 raw relu out (205 MB)
__device__ float g_h2[(size_t)NB*NE*7*7*NC];     // conv2 raw relu out
__device__ float g_h3[(size_t)NB*NE*4*4*NC];     // conv3 raw relu out
__device__ float g_feat[NB*NE*NC];               // max-pooled raw conv4 relu
__device__ float g_kT[3][NB][9][64][64];         // weights transposed to [co][ci]
__device__ float g_sum[4*NC];
__device__ float g_sumsq[4*NC];
__device__ float g_scale[4*NC];                  // rsqrt(var+eps)
__device__ float g_bias[4*NC];                   // -mean*scale

__device__ __forceinline__ uint32_t smem_u32(const void* p) {
    return (uint32_t)__cvta_generic_to_shared(p);
}
__device__ __forceinline__ uint32_t pb(__nv_bfloat16 a, __nv_bfloat16 b) {
    unsigned short ua = *(unsigned short*)&a, ub = *(unsigned short*)&b;
    return (uint32_t)ua | ((uint32_t)ub << 16);
}

#define MMA_BF16(acc, A0,A1,A2,A3, B0,B1) \
    asm volatile("mma.sync.aligned.m16n8k16.row.col.f32.bf16.bf16.f32 " \
        "{%0,%1,%2,%3}, {%4,%5,%6,%7}, {%8,%9}, {%0,%1,%2,%3};" \
        : "+f"(acc[0]),"+f"(acc[1]),"+f"(acc[2]),"+f"(acc[3]) \
        : "r"(A0),"r"(A1),"r"(A2),"r"(A3), "r"(B0),"r"(B1))

#define LDMATRIX_X4(r0,r1,r2,r3, addr) \
    asm volatile("ldmatrix.sync.aligned.m8n8.x4.shared.b16 {%0,%1,%2,%3}, [%4];" \
        : "=r"(r0),"=r"(r1),"=r"(r2),"=r"(r3) : "r"(addr))

#define LDS32(r, addr) \
    asm volatile("ld.shared.b32 %0, [%1];" : "=r"(r) : "r"(addr))

// ---------------- zero stats + feat ----------------
__global__ void zero_kernel() {
    int i = blockIdx.x * 256 + threadIdx.x;
    if (i < 4*NC) { g_sum[i] = 0.f; g_sumsq[i] = 0.f; }
    if (i < NB*NE*NC) g_feat[i] = 0.f;
}

// ---------------- weight transpose: kw[b][kk][ci][co] -> g_kT[layer][b][kk][co][ci] ----------------
__global__ __launch_bounds__(256) void wtrans_kernel(const float* __restrict__ k2,
                                                     const float* __restrict__ k3,
                                                     const float* __restrict__ k4) {
    __shared__ float s[64*65];
    int layer = blockIdx.y;
    const float* kw = (layer==0) ? k2 : (layer==1) ? k3 : k4;
    int b  = blockIdx.x >> 4;
    int kk = blockIdx.x & 15;
    if (kk >= 9) return;
    int t = threadIdx.x;
    const float* src = kw + ((size_t)b*9 + kk)*4096;
    #pragma unroll
    for (int p = 0; p < 16; p++) {
        int idx = p*256 + t;           // idx = ci*64 + co
        int ci = idx >> 6, co = idx & 63;
        s[co*65 + ci] = src[idx];
    }
    __syncthreads();
    float* dst = &g_kT[layer][b][kk][0][0];
    #pragma unroll
    for (int p = 0; p < 16; p++) {
        int idx = p*256 + t;           // idx = co*64 + ci
        int co = idx >> 6, ci = idx & 63;
        dst[idx] = s[co*65 + ci];
    }
}

// ---------------- conv1: Cin=1, 28x28 -> 14x14x64 ----------------
__global__ __launch_bounds__(256) void conv1_kernel(const float* __restrict__ x,
                                                    const float* __restrict__ k1) {
    __shared__ float s_in[30*30];
    __shared__ float s_sum[NC];
    __shared__ float s_sq[NC];
    int be = blockIdx.x;
    int t = threadIdx.x;
    for (int i = t; i < 900; i += 256) s_in[i] = 0.f;
    if (t < NC) { s_sum[t] = 0.f; s_sq[t] = 0.f; }
    __syncthreads();
    const float* xp = x + (size_t)be * 784;
    for (int i = t; i < 784; i += 256) {
        int r = i / 28, c = i - r*28;
        s_in[(r+1)*30 + c + 1] = xp[i];
    }
    int cg = t & 15, ig = t >> 4;
    int b = be >> 6;
    float4 w[9];
    const float4* kp = (const float4*)(k1 + (size_t)b * 576);
    #pragma unroll
    for (int j = 0; j < 9; j++) w[j] = kp[j*16 + cg];
    __syncthreads();
    float ls0=0,ls1=0,ls2=0,ls3=0, lq0=0,lq1=0,lq2=0,lq3=0;
    float* outp = g_h1 + (size_t)be * 196 * 64;
    for (int p = ig; p < 196; p += 16) {
        int oy = p / 14, ox = p - oy*14;
        float a0=0,a1=0,a2=0,a3=0;
        #pragma unroll
        for (int ky = 0; ky < 3; ky++)
        #pragma unroll
        for (int kx = 0; kx < 3; kx++) {
            float v = s_in[(2*oy+ky)*30 + 2*ox + kx];
            float4 ww = w[ky*3+kx];
            a0 = fmaf(v, ww.x, a0); a1 = fmaf(v, ww.y, a1);
            a2 = fmaf(v, ww.z, a2); a3 = fmaf(v, ww.w, a3);
        }
        a0 = fmaxf(a0, 0.f); a1 = fmaxf(a1, 0.f);
        a2 = fmaxf(a2, 0.f); a3 = fmaxf(a3, 0.f);
        ls0+=a0; ls1+=a1; ls2+=a2; ls3+=a3;
        lq0+=a0*a0; lq1+=a1*a1; lq2+=a2*a2; lq3+=a3*a3;
        ((float4*)(outp + p*64))[cg] = make_float4(a0,a1,a2,a3);
    }
    int co4 = cg*4;
    atomicAdd(&s_sum[co4+0], ls0); atomicAdd(&s_sum[co4+1], ls1);
    atomicAdd(&s_sum[co4+2], ls2); atomicAdd(&s_sum[co4+3], ls3);
    atomicAdd(&s_sq[co4+0], lq0); atomicAdd(&s_sq[co4+1], lq1);
    atomicAdd(&s_sq[co4+2], lq2); atomicAdd(&s_sq[co4+3], lq3);
    __syncthreads();
    if (t < NC) {
        atomicAdd(&g_sum[t], s_sum[t]);
        atomicAdd(&g_sumsq[t], s_sq[t]);
    }
}

// ---------------- per-layer BN stats finalize ----------------
__global__ void finalize_kernel(int layer, float invN) {
    int c = threadIdx.x;
    float s = g_sum[layer*NC + c];
    float q = g_sumsq[layer*NC + c];
    float m = s * invN;
    float v = q * invN - m*m;
    float sc = rsqrtf(v + 1e-3f);
    g_scale[layer*NC + c] = sc;
    g_bias[layer*NC + c] = -m * sc;
}

// ---------------- conv layers 2-4: mma.sync bf16-split implicit GEMM ----------------
// Per block: M-tile 128 (8 warps x m16), N=64, K=576 in 9 chunks of 64.
// A = im2col(BN-folded prev activations), B = g_kT [co][ci].
// Row stride in smem: 72 bf16 = 144 bytes (16B aligned, conflict-free phases).
template<int LNUM>
__global__ __launch_bounds__(256, 2) void conv_kernel() {
    constexpr int HIN  = (LNUM==1) ? 14 : (LNUM==2) ? 7 : 4;
    constexpr int HOUT = (LNUM==1) ? 7  : (LNUM==2) ? 4 : 2;
    constexpr int SPREV = LNUM - 1;
    constexpr bool LAST = (LNUM==3);
    constexpr int POS   = HOUT*HOUT;
    constexpr int MTASK = NE*POS;
    constexpr int RS    = 144;                 // row stride bytes
    constexpr int AHI_O = 0, ALO_O = 128*RS, BHI_O = 2*128*RS, BLO_O = 2*128*RS + 64*RS;

    __shared__ float s_sc[64], s_bi[64], s_sum[64], s_sq[64];
    __shared__ int s_ri[128];
    extern __shared__ char dsm[];

    int b = blockIdx.y, m0 = blockIdx.x*128, t = threadIdx.x;
    int wid = t >> 5, lane = t & 31;

    if (t < 64) {
        s_sc[t] = g_scale[SPREV*NC + t];
        s_bi[t] = g_bias[SPREV*NC + t];
        s_sum[t] = 0.f; s_sq[t] = 0.f;
    }
    if (t < 128) {
        int gic = min(m0 + t, MTASK-1);
        int e = gic / POS, p = gic - e*POS;
        s_ri[t] = (e << 16) | ((p / HOUT) << 8) | (p % HOUT);
    }
    __syncthreads();

    const float* wT = &g_kT[LNUM-1][b][0][0][0];
    const float* taskin = ((LNUM==1) ? g_h1 : (LNUM==2) ? g_h2 : g_h3)
                        + (size_t)b*NE*HIN*HIN*64;
    float* h_out = (LNUM==1) ? g_h2 : g_h3;

    // loader assignment: 16 threads per row, thread covers 4 channels (float4)
    int lr = t >> 4;     // row within 16-row pass
    int lj = t & 15;     // channel group
    float4 f_s = ((const float4*)s_sc)[lj];
    float4 f_b = ((const float4*)s_bi)[lj];

    // mma addressing
    uint32_t smem0 = smem_u32(dsm);
    uint32_t a_base = smem0 + AHI_O + (wid*16)*RS + (lane & 15)*RS + ((lane >> 4) * 16);
    // B fragment (m16n8k16 col-major): lane reads column n = lane>>2, k pair (lane&3)*2.
    // Row (cout) address = (nt*8 + (lane>>2))*RS; k offset (lane&3)*4 bytes; +16B for k+8.
    uint32_t b_base = smem0 + BHI_O + (lane >> 2)*RS + (lane & 3)*4;

    float acc[8][4];
    #pragma unroll
    for (int nt = 0; nt < 8; nt++)
        #pragma unroll
        for (int j = 0; j < 4; j++) acc[nt][j] = 0.f;

    for (int kk = 0; kk < 9; kk++) {
        int ky = kk/3, kx = kk - ky*3;
        // ---- B tile: g_kT [co][ci] fp32 -> split bf16 hi/lo ----
        #pragma unroll
        for (int p = 0; p < 4; p++) {
            int row = p*16 + lr;
            float4 v = ((const float4*)(wT + kk*4096 + row*64))[lj];
            __nv_bfloat16 h0=__float2bfloat16(v.x), h1=__float2bfloat16(v.y),
                          h2=__float2bfloat16(v.z), h3=__float2bfloat16(v.w);
            __nv_bfloat16 l0=__float2bfloat16(v.x-__bfloat162float(h0)),
                          l1=__float2bfloat16(v.y-__bfloat162float(h1)),
                          l2=__float2bfloat16(v.z-__bfloat162float(h2)),
                          l3=__float2bfloat16(v.w-__bfloat162float(h3));
            *(uint2*)(dsm + BHI_O + row*RS + lj*8) = make_uint2(pb(h0,h1), pb(h2,h3));
            *(uint2*)(dsm + BLO_O + row*RS + lj*8) = make_uint2(pb(l0,l1), pb(l2,l3));
        }
        // ---- A tile: coalesced im2col + BN-fold -> split bf16 hi/lo ----
        #pragma unroll
        for (int rr = 0; rr < 8; rr++) {
            int row = rr*16 + lr;
            int info = s_ri[row];
            int e = info >> 16, oy = (info >> 8) & 255, ox = info & 255;
            int iy = 2*oy - 1 + ky;
            int ix = 2*ox - 1 + kx;
            float4 v = make_float4(0.f,0.f,0.f,0.f);
            if ((unsigned)iy < (unsigned)HIN && (unsigned)ix < (unsigned)HIN) {
                v = ((const float4*)(taskin + ((size_t)e*HIN*HIN + iy*HIN + ix)*64))[lj];
                v.x = fmaf(v.x, f_s.x, f_b.x);
                v.y = fmaf(v.y, f_s.y, f_b.y);
                v.z = fmaf(v.z, f_s.z, f_b.z);
                v.w = fmaf(v.w, f_s.w, f_b.w);
            }
            __nv_bfloat16 h0=__float2bfloat16(v.x), h1=__float2bfloat16(v.y),
                          h2=__float2bfloat16(v.z), h3=__float2bfloat16(v.w);
            __nv_bfloat16 l0=__float2bfloat16(v.x-__bfloat162float(h0)),
                          l1=__float2bfloat16(v.y-__bfloat162float(h1)),
                          l2=__float2bfloat16(v.z-__bfloat162float(h2)),
                          l3=__float2bfloat16(v.w-__bfloat162float(h3));
            *(uint2*)(dsm + AHI_O + row*RS + lj*8) = make_uint2(pb(h0,h1), pb(h2,h3));
            *(uint2*)(dsm + ALO_O + row*RS + lj*8) = make_uint2(pb(l0,l1), pb(l2,l3));
        }
        __syncthreads();
        // ---- MMA: 4 k16-steps; per step: A frags (hi,lo) + 8 n-tiles x 3 terms ----
        #pragma unroll
        for (int ks = 0; ks < 4; ks++) {
            uint32_t ah0,ah1,ah2,ah3, al0,al1,al2,al3;
            LDMATRIX_X4(ah0,ah1,ah2,ah3, a_base + ks*32);
            LDMATRIX_X4(al0,al1,al2,al3, a_base + (ALO_O - AHI_O) + ks*32);
            #pragma unroll
            for (int nt = 0; nt < 8; nt++) {
                uint32_t bh0,bh1,bl0,bl1;
                uint32_t ba = b_base + nt*8*RS + ks*32;   // FIXED: row = nt*8 + (lane>>2)
                LDS32(bh0, ba);
                LDS32(bh1, ba + 16);
                LDS32(bl0, ba + (BLO_O - BHI_O));
                LDS32(bl1, ba + (BLO_O - BHI_O) + 16);
                MMA_BF16(acc[nt], ah0,ah1,ah2,ah3, bh0,bh1);
                MMA_BF16(acc[nt], ah0,ah1,ah2,ah3, bl0,bl1);
                MMA_BF16(acc[nt], al0,al1,al2,al3, bh0,bh1);
            }
        }
        __syncthreads();
    }

    // ---- epilogue: relu, BN stats (shfl-reduced), store / max-pool ----
    int q  = lane & 3;
    int r0 = lane >> 2;
    int g0 = m0 + wid*16 + r0;
    int g1 = g0 + 8;
    bool v0 = g0 < MTASK, v1 = g1 < MTASK;
    float lsum[16], lsq[16];
    #pragma unroll
    for (int nt = 0; nt < 8; nt++) {
        float d0 = v0 ? fmaxf(acc[nt][0], 0.f) : 0.f;
        float d1 = v0 ? fmaxf(acc[nt][1], 0.f) : 0.f;
        float d2 = v1 ? fmaxf(acc[nt][2], 0.f) : 0.f;
        float d3 = v1 ? fmaxf(acc[nt][3], 0.f) : 0.f;
        lsum[2*nt]   = d0 + d2;  lsq[2*nt]   = d0*d0 + d2*d2;
        lsum[2*nt+1] = d1 + d3;  lsq[2*nt+1] = d1*d1 + d3*d3;
        int col = nt*8 + q*2;
        if (!LAST) {
            if (v0) *(float2*)(h_out + ((size_t)b*MTASK + g0)*64 + col) = make_float2(d0, d1);
            if (v1) *(float2*)(h_out + ((size_t)b*MTASK + g1)*64 + col) = make_float2(d2, d3);
        } else {
            if (v0) {
                int* fp = (int*)(g_feat + (size_t)(b*NE + g0/POS)*64 + col);
                atomicMax(&fp[0], __float_as_int(d0));
                atomicMax(&fp[1], __float_as_int(d1));
            }
            if (v1) {
                int* fp = (int*)(g_feat + (size_t)(b*NE + g1/POS)*64 + col);
                atomicMax(&fp[0], __float_as_int(d2));
                atomicMax(&fp[1], __float_as_int(d3));
            }
        }
    }
    // reduce over the 8 lanes sharing q (xor 4,8,16 vary lane>>2)
    #pragma unroll
    for (int j = 0; j < 16; j++) {
        #pragma unroll
        for (int o = 4; o <= 16; o <<= 1) {
            lsum[j] += __shfl_xor_sync(0xFFFFFFFFu, lsum[j], o);
            lsq[j]  += __shfl_xor_sync(0xFFFFFFFFu, lsq[j],  o);
        }
    }
    if (lane < 4) {
        #pragma unroll
        for (int nt = 0; nt < 8; nt++) {
            int col = nt*8 + q*2;
            atomicAdd(&s_sum[col],   lsum[2*nt]);
            atomicAdd(&s_sum[col+1], lsum[2*nt+1]);
            atomicAdd(&s_sq[col],    lsq[2*nt]);
            atomicAdd(&s_sq[col+1],  lsq[2*nt+1]);
        }
    }
    __syncthreads();
    if (t < 64) {
        atomicAdd(&g_sum[LNUM*NC + t],   s_sum[t]);
        atomicAdd(&g_sumsq[LNUM*NC + t], s_sq[t]);
    }
}

// ---------------- readout: normalize pooled feats, per-task matmul ----------------
__global__ __launch_bounds__(256) void readout_kernel(const float* __restrict__ w_ro,
                                                      float* __restrict__ out) {
    __shared__ float s_w[64*20];
    __shared__ float s_f[64*64];
    int b = blockIdx.x, t = threadIdx.x;
    for (int i = t; i < 1280; i += 256) s_w[i] = w_ro[(size_t)b*1280 + i];
    const float* fp = g_feat + (size_t)b*4096;
    for (int i = t; i < 4096; i += 256) {
        int c = i & 63;
        s_f[i] = fmaf(fp[i], g_scale[3*64+c], g_bias[3*64+c]);
    }
    __syncthreads();
    for (int idx = t; idx < 1280; idx += 256) {
        int e = idx/20, o = idx - e*20;
        float s = 0.f;
        const float* fe = s_f + e*64;
        #pragma unroll 16
        for (int c = 0; c < 64; c++) s = fmaf(fe[c], s_w[c*20+o], s);
        out[(size_t)b*1280 + idx] = s;
    }
}

// ---------------- launch ----------------
extern "C" void kernel_launch(void* const* d_in, const int* in_sizes, int n_in,
                              void* d_out, int out_size) {
    const float* x  = (const float*)d_in[0];
    const float* k1 = (const float*)d_in[1];
    const float* k2 = (const float*)d_in[2];
    const float* k3 = (const float*)d_in[3];
    const float* k4 = (const float*)d_in[4];
    const float* w  = (const float*)d_in[5];
    float* out = (float*)d_out;
    (void)in_sizes; (void)n_in; (void)out_size;

    const int dsmem = 2*128*144 + 2*64*144;   // A hi/lo + B hi/lo = 55296 B
    cudaFuncSetAttribute(conv_kernel<1>, cudaFuncAttributeMaxDynamicSharedMemorySize, dsmem);
    cudaFuncSetAttribute(conv_kernel<2>, cudaFuncAttributeMaxDynamicSharedMemorySize, dsmem);
    cudaFuncSetAttribute(conv_kernel<3>, cudaFuncAttributeMaxDynamicSharedMemorySize, dsmem);

    zero_kernel<<<1024, 256>>>();
    wtrans_kernel<<<dim3(64*16, 3), 256>>>(k2, k3, k4);
    conv1_kernel<<<NB*NE, 256>>>(x, k1);
    finalize_kernel<<<1, 64>>>(0, 1.f/(NB*NE*196.f));
    conv_kernel<1><<<dim3(25, NB), 256, dsmem>>>();
    finalize_kernel<<<1, 64>>>(1, 1.f/(NB*NE*49.f));
    conv_kernel<2><<<dim3(8, NB), 256, dsmem>>>();
    finalize_kernel<<<1, 64>>>(2, 1.f/(NB*NE*16.f));
    conv_kernel<3><<<dim3(2, NB), 256, dsmem>>>();
    finalize_kernel<<<1, 64>>>(3, 1.f/(NB*NE*4.f));
    readout_kernel<<<NB, 256>>>(w, out);
}